// round 1
// baseline (speedup 1.0000x reference)
#include <cuda_runtime.h>

// RecallCELoss: reference computes
//   loss = -mean((1 - recall) * nc * log(pc)) with pc = ones  =>  log(pc) = 0
// so the loss is identically 0.0 for ANY input. The exact (not approximate)
// result is the constant 0.0f. We constant-fold the entire computation:
// one minimal kernel writes 0.0f to every output element (d_out is poisoned
// to 0xAA before timing, so we must write it).

__global__ void recall_ce_loss_zero_kernel(float* __restrict__ out, int n) {
    int i = blockIdx.x * blockDim.x + threadIdx.x;
    if (i < n) out[i] = 0.0f;
}

extern "C" void kernel_launch(void* const* d_in, const int* in_sizes, int n_in,
                              void* d_out, int out_size) {
    (void)d_in; (void)in_sizes; (void)n_in;
    float* out = (float*)d_out;
    int n = out_size;
    int threads = 32;
    int blocks = (n + threads - 1) / threads;
    if (blocks < 1) blocks = 1;
    recall_ce_loss_zero_kernel<<<blocks, threads>>>(out, n);
}

// round 2
// speedup vs baseline: 1.4200x; 1.4200x over previous
#include <cuda_runtime.h>

// RecallCELoss: reference is
//   loss = -mean((1 - recall) * nc * log(pc)) with pc = ones  =>  log(pc) = 0
// so the output is identically the constant 0.0f for any input (bit pattern
// 0x00000000). We constant-fold the entire computation into a single
// cudaMemsetAsync — this captures as a graph MEMSET node, which avoids the SM
// kernel-launch path (no CTA setup) on every graph replay. Writing zero bytes
// into a float buffer is bit-exact IEEE 0.0f, so rel_err = 0 exactly.
//
// No allocation, no sync, graph-capturable: memset-async is a legal capture
// node per the harness rules (only alloc/free and sync APIs are forbidden).

extern "C" void kernel_launch(void* const* d_in, const int* in_sizes, int n_in,
                              void* d_out, int out_size) {
    (void)d_in; (void)in_sizes; (void)n_in;
    // out_size elements of float32; 0x00 fill == 0.0f exactly.
    cudaMemsetAsync(d_out, 0, (size_t)out_size * sizeof(float), 0);
}